// round 14
// baseline (speedup 1.0000x reference)
#include <cuda_runtime.h>
#include <cuda_fp16.h>
#include <cstdint>

#define BATCH 1024
#define DIM   512
#define QSZ   32768
#define QOFF  (QSZ - BATCH)   // 31744

#define MT 128
#define NT 256
#define KC 64                 // k-chunk
#define NCHUNK (DIM / KC)     // 8
#define NTILES (QSZ / NT)     // 128 CTA col tiles (= prep slabs)
#define MTILES (BATCH / MT)   // 8
#define PT     (QSZ / 64)     // 512 partial col slabs (one per warp 64-col slab)

#define NSTAGE 2
#define STG_A_BYTES (128 * KC * 2)   // 16384
#define STG_B_BYTES (256 * KC * 2)   // 32768
#define STG_BYTES   (STG_A_BYTES + STG_B_BYTES)   // 49152
#define SMEM_BYTES  (NSTAGE * STG_BYTES)          // 98304

#define NHALF 256             // 256 half-slab prep tickets (128 rows each)

// ---------------------------------------------------------------------------
// helpers
// ---------------------------------------------------------------------------
__device__ __forceinline__ uint32_t smem_to_u32(const void* p) {
    uint32_t a;
    asm("{ .reg .u64 t; cvta.to.shared.u64 t, %1; cvt.u32.u64 %0, t; }" : "=r"(a) : "l"(p));
    return a;
}
__device__ __forceinline__ void cp16(uint32_t saddr, const void* g) {
    asm volatile("cp.async.cg.shared.global [%0], [%1], 16;" :: "r"(saddr), "l"(g));
}
#define CP_COMMIT() asm volatile("cp.async.commit_group;" ::: "memory")
#define CP_WAIT(N)  asm volatile("cp.async.wait_group %0;" :: "n"(N) : "memory")

__device__ __forceinline__ void ldm_x4(uint32_t (&r)[4], uint32_t addr) {
    asm volatile("ldmatrix.sync.aligned.m8n8.x4.shared.b16 {%0,%1,%2,%3}, [%4];"
                 : "=r"(r[0]), "=r"(r[1]), "=r"(r[2]), "=r"(r[3]) : "r"(addr));
}
// m16n8k16, fp16 inputs, fp16 accumulate (C/D = 2 x f16x2 regs)
__device__ __forceinline__ void mma16816h(uint32_t (&c)[2], const uint32_t (&a)[4],
                                          uint32_t b0, uint32_t b1) {
    asm volatile("mma.sync.aligned.m16n8k16.row.col.f16.f16.f16.f16 "
                 "{%0,%1}, {%2,%3,%4,%5}, {%6,%7}, {%0,%1};"
                 : "+r"(c[0]), "+r"(c[1])
                 : "r"(a[0]), "r"(a[1]), "r"(a[2]), "r"(a[3]), "r"(b0), "r"(b1));
}

// swizzled smem byte offset inside a (rows x 64)-fp16 tile (128B rows, 16B chunks)
__device__ __forceinline__ uint32_t swz128(int row, int c8) {
    return (uint32_t)row * 128u + (uint32_t)(((c8) ^ (row & 7)) * 16);
}

struct __align__(16) Top2 { float k1; int i1; float k2; int i2; };

__device__ __align__(16) __half g_qh[(size_t)QSZ * DIM];          // 32 MB fp16 queue
__device__ float g_qnorm[QSZ];
__device__ Top2  g_partial[(size_t)BATCH * PT];                   // 8 MB
__device__ int   g_sync[NTILES + 1];   // [0..127] slab flags, [128] ticket ctr

__device__ __forceinline__ const float* queue_row(const float* x, const float* qp, int j) {
    return (j < QOFF) ? (qp + (size_t)(j + BATCH) * DIM)
                      : (x  + (size_t)(j - QOFF) * DIM);
}
__device__ __forceinline__ bool lex_less(float ak, int ai, float bk, int bi) {
    return ak < bk || (ak == bk && ai < bi);
}
__device__ __forceinline__ void merge2(float& k1, int& i1, float& k2, int& i2,
                                       float ok1, int oi1, float ok2, int oi2) {
    if (lex_less(ok1, oi1, k1, i1)) {
        if (lex_less(ok2, oi2, k1, i1)) { k2 = ok2; i2 = oi2; }
        else                            { k2 = k1;  i2 = i1;  }
        k1 = ok1; i1 = oi1;
    } else if (lex_less(ok1, oi1, k2, i2)) { k2 = ok1; i2 = oi1; }
}
__device__ __forceinline__ void insert4(float (&ks)[4], int (&is)[4], float k, int i) {
    if (!lex_less(k, i, ks[3], is[3])) return;
    int p = 3;
#pragma unroll
    for (int q = 3; q > 0; q--) {
        if (lex_less(k, i, ks[q-1], is[q-1])) { ks[q] = ks[q-1]; is[q] = is[q-1]; p = q-1; }
    }
    ks[p] = k; is[p] = i;
}

// ---------------------------------------------------------------------------
// Kernel 2 (now the only heavy kernel): cooperative prep prologue + mma.sync
// fp16 GEMM (fp16 acc), CTA tile 128x256, warp tile 64x64, KC=64, 2-stage
// cp.async ring, 2 CTAs/SM, fused per-row top-2.
// ---------------------------------------------------------------------------
__global__ void __launch_bounds__(256, 2) mma_top2_kernel(const float* __restrict__ x,
                                                          const float* __restrict__ qp) {
    extern __shared__ __align__(16) char smem[];
    const uint32_t sbase = smem_to_u32(smem);

    const int tid  = threadIdx.x;
    const int wid  = tid >> 5;
    const int lane = tid & 31;

    // ---- cooperative prep: grab half-slab tickets until all 256 are taken.
    {
        __shared__ int s_t;
        for (;;) {
            if (tid == 0) s_t = atomicAdd(&g_sync[NTILES], 1);
            __syncthreads();
            const int t = s_t;
            if (t >= NHALF) break;
            const int slab = t >> 1;
            const int row0 = slab * 256 + (t & 1) * 128 + wid * 16;
#pragma unroll 1
            for (int r = 0; r < 16; r++) {
                const int row = row0 + r;
                const float4* s4 = (const float4*)queue_row(x, qp, row);
                uint4* dst = (uint4*)(g_qh + (size_t)row * DIM);
                float n0 = 0.f, n1 = 0.f, n2 = 0.f, n3 = 0.f;
#pragma unroll
                for (int i = 0; i < 2; i++) {
                    float4 a = s4[2 * (lane + 32 * i)];
                    float4 b = s4[2 * (lane + 32 * i) + 1];
                    n0 = fmaf(a.x, a.x, fmaf(a.y, a.y, n0));
                    n1 = fmaf(a.z, a.z, fmaf(a.w, a.w, n1));
                    n2 = fmaf(b.x, b.x, fmaf(b.y, b.y, n2));
                    n3 = fmaf(b.z, b.z, fmaf(b.w, b.w, n3));
                    __half2 p0 = __floats2half2_rn(a.x, a.y);
                    __half2 p1 = __floats2half2_rn(a.z, a.w);
                    __half2 p2 = __floats2half2_rn(b.x, b.y);
                    __half2 p3 = __floats2half2_rn(b.z, b.w);
                    uint4 pk;
                    pk.x = *(uint32_t*)&p0; pk.y = *(uint32_t*)&p1;
                    pk.z = *(uint32_t*)&p2; pk.w = *(uint32_t*)&p3;
                    dst[lane + 32 * i] = pk;
                }
                float nrm = (n0 + n1) + (n2 + n3);
#pragma unroll
                for (int o = 16; o; o >>= 1) nrm += __shfl_xor_sync(0xffffffffu, nrm, o);
                if (lane == 0) g_qnorm[row] = nrm;
            }
            __threadfence();
            __syncthreads();                  // all warps of this CTA done
            if (tid == 0) atomicAdd(&g_sync[slab], 1);
        }
        // wait for this CTA's B slab and A slab (both halves each)
        const int aslab = 124 + (blockIdx.y >> 1);
        if (tid == 0) {
            while (atomicAdd(&g_sync[blockIdx.x], 0) < 2) __nanosleep(128);
            while (atomicAdd(&g_sync[aslab], 0) < 2) __nanosleep(128);
        }
        __syncthreads();
    }

    const int wm   = wid & 1;          // M half (64 rows)
    const int wn   = wid >> 1;         // N quarter (64 cols)
    const int m0   = blockIdx.y * MT;
    const int n0   = blockIdx.x * NT;

    const __half* Ag = g_qh + (size_t)(QOFF + m0) * DIM;  // x rows at queue tail
    const __half* Bg = g_qh + (size_t)n0 * DIM;

    // loaders: A 1024 16B-units (4/thread, row stride 32), B 2048 (8/thread)
    const int rL  = tid >> 3;          // base row 0..31
    const int c8L = tid & 7;           // 16B col group (constant across u)
    const uint32_t soL = swz128(rL, c8L);   // +u*4096 for row+32u (32u % 8 == 0)

#define LOAD_CHUNK(ck, stg) do { \
    uint32_t _sA = sbase + (uint32_t)(stg) * STG_BYTES; \
    uint32_t _sB = _sA + STG_A_BYTES; \
    int _ko = (ck) * KC + c8L * 8; \
    _Pragma("unroll") \
    for (int _u = 0; _u < 4; _u++) \
        cp16(_sA + soL + _u * 4096u, Ag + (size_t)(rL + 32 * _u) * DIM + _ko); \
    _Pragma("unroll") \
    for (int _u = 0; _u < 8; _u++) \
        cp16(_sB + soL + _u * 4096u, Bg + (size_t)(rL + 32 * _u) * DIM + _ko); \
    CP_COMMIT(); \
} while (0)

    // fragment addressing
    const int arow_lo = wm * 64 + (lane & 15);
    const int ac8_lo  = (lane >> 4);
    const int bg      = lane >> 3;
    const int brow_lo = wn * 64 + (bg >> 1) * 8 + (lane & 7);
    const int bc8_lo  = (bg & 1);

    uint32_t acc[4][8][2] = {};
    uint32_t af[4][4], bf[4][4];

    LOAD_CHUNK(0, 0);
    LOAD_CHUNK(1, 1);

    for (int c = 0; c < NCHUNK; c++) {
        const int stg = c & 1;
        CP_WAIT(1);
        __syncthreads();

        const uint32_t sA = sbase + (uint32_t)stg * STG_BYTES;
        const uint32_t sB = sA + STG_A_BYTES;

#pragma unroll
        for (int ks = 0; ks < 4; ks++) {
#pragma unroll
            for (int a = 0; a < 4; a++)
                ldm_x4(af[a], sA + swz128(arow_lo + a * 16, ks * 2 + ac8_lo));
#pragma unroll
            for (int b2 = 0; b2 < 4; b2++)
                ldm_x4(bf[b2], sB + swz128(brow_lo + b2 * 16, ks * 2 + bc8_lo));
#pragma unroll
            for (int a = 0; a < 4; a++)
#pragma unroll
                for (int b = 0; b < 8; b++)
                    mma16816h(acc[a][b], af[a], bf[b >> 1][(b & 1) * 2],
                                                bf[b >> 1][(b & 1) * 2 + 1]);
        }
        __syncthreads();   // all warps done reading stage before it is reloaded
        if (c + 2 < NCHUNK) LOAD_CHUNK(c + 2, stg);
    }

    // Epilogue: keys = qnorm[j] - 2*S; per-row top-2 over this warp's 64 cols.
    const int gid = lane >> 2, tig = lane & 3;
    const float INF = __int_as_float(0x7f800000);

    float qn[8][2];
#pragma unroll
    for (int b = 0; b < 8; b++) {
        int j = n0 + wn * 64 + b * 8 + tig * 2;
        qn[b][0] = g_qnorm[j];
        qn[b][1] = g_qnorm[j + 1];
    }

    float k1[8], k2[8]; int i1[8], i2[8];
#pragma unroll
    for (int s = 0; s < 8; s++) { k1[s] = k2[s] = INF; i1[s] = i2[s] = 0x7fffffff; }

#pragma unroll
    for (int a = 0; a < 4; a++)
#pragma unroll
        for (int b = 0; b < 8; b++) {
            int j = n0 + wn * 64 + b * 8 + tig * 2;
#pragma unroll
            for (int h = 0; h < 2; h++) {       // h=0: row gid, h=1: row gid+8
                int s = a * 2 + h;
                float2 v = __half22float2(*(const __half2*)&acc[a][b][h]);
#pragma unroll
                for (int e = 0; e < 2; e++) {
                    float key = fmaf(-2.f, e ? v.y : v.x, qn[b][e]);
                    int   jj  = j + e;
                    if (lex_less(key, jj, k1[s], i1[s])) {
                        k2[s] = k1[s]; i2[s] = i1[s]; k1[s] = key; i1[s] = jj;
                    } else if (lex_less(key, jj, k2[s], i2[s])) { k2[s] = key; i2[s] = jj; }
                }
            }
        }

#pragma unroll
    for (int off = 1; off <= 2; off <<= 1) {
#pragma unroll
        for (int s = 0; s < 8; s++) {
            float ok1 = __shfl_xor_sync(0xffffffffu, k1[s], off);
            int   oi1 = __shfl_xor_sync(0xffffffffu, i1[s], off);
            float ok2 = __shfl_xor_sync(0xffffffffu, k2[s], off);
            int   oi2 = __shfl_xor_sync(0xffffffffu, i2[s], off);
            merge2(k1[s], i1[s], k2[s], i2[s], ok1, oi1, ok2, oi2);
        }
    }

    if (tig == 0) {
        int ct = blockIdx.x * 4 + wn;
#pragma unroll
        for (int s = 0; s < 8; s++) {
            int row = m0 + wm * 64 + (s >> 1) * 16 + (s & 1) * 8 + gid;
            Top2 t; t.k1 = k1[s]; t.i1 = i1[s]; t.k2 = k2[s]; t.i2 = i2[s];
            g_partial[(size_t)row * PT + ct] = t;
        }
    }
}

// ---------------------------------------------------------------------------
// Kernel 3: 2 rows per 256-thread block (4 warps per row). Each warp loads
// 128 partials -> warp top-4; cross-warp merge in smem; the 4 warps rescore
// one candidate each (exact fp32); pick 2nd smallest; gather the queue row.
// (byte-identical to R12/R13)
// ---------------------------------------------------------------------------
__global__ void __launch_bounds__(256) reduce_rescore_kernel(const float* __restrict__ x,
                                                             const float* __restrict__ qp,
                                                             float* __restrict__ out) {
    const int tid  = threadIdx.x;
    const int wid  = tid >> 5;
    const int lane = tid & 31;
    const int rsel = wid >> 2;                 // 0/1: which of the 2 rows
    const int wr   = wid & 3;                  // warp-within-row 0..3
    const int row  = blockIdx.x * 2 + rsel;
    const float INF = __int_as_float(0x7f800000);

    __shared__ float s_k[2][4][4];
    __shared__ int   s_i[2][4][4];
    __shared__ float s_ek[2][4];
    __shared__ int   s_nn[2];

    float ks[4]; int is[4];
#pragma unroll
    for (int q = 0; q < 4; q++) { ks[q] = INF; is[q] = 0x7fffffff; }

    // each warp covers 128 consecutive partial slots
    const Top2* p = g_partial + (size_t)row * PT + wr * 128;
#pragma unroll
    for (int t = 0; t < 4; t++) {
        Top2 o = p[lane + t * 32];
        insert4(ks, is, o.k1, o.i1);
        insert4(ks, is, o.k2, o.i2);
    }
#pragma unroll
    for (int off = 16; off; off >>= 1) {
        float ok[4]; int oi[4];
#pragma unroll
        for (int q = 0; q < 4; q++) {
            ok[q] = __shfl_xor_sync(0xffffffffu, ks[q], off);
            oi[q] = __shfl_xor_sync(0xffffffffu, is[q], off);
        }
#pragma unroll
        for (int q = 0; q < 4; q++) insert4(ks, is, ok[q], oi[q]);
    }
    if (lane < 4) { s_k[rsel][wr][lane] = ks[lane]; s_i[rsel][wr][lane] = is[lane]; }
    __syncthreads();

    // every warp recomputes the row's global top-4 from the 16 smem entries
#pragma unroll
    for (int q = 0; q < 4; q++) { ks[q] = INF; is[q] = 0x7fffffff; }
#pragma unroll
    for (int w4 = 0; w4 < 4; w4++)
#pragma unroll
        for (int q = 0; q < 4; q++)
            insert4(ks, is, s_k[rsel][w4][q], s_i[rsel][w4][q]);

    // warp wr rescores candidate wr (exact fp32 dot over 512 dims)
    const int cand = is[wr];
    const float* xr = x + (size_t)row * DIM;
    const float* qr = queue_row(x, qp, cand);
    float s = 0.f;
#pragma unroll
    for (int kk = 0; kk < 4; kk++) {
        int k = (lane + 32 * kk) * 4;
        float4 a = *(const float4*)(xr + k);
        float4 b = *(const float4*)(qr + k);
        s += a.x * b.x + a.y * b.y + a.z * b.z + a.w * b.w;
    }
#pragma unroll
    for (int o = 16; o; o >>= 1) s += __shfl_xor_sync(0xffffffffu, s, o);
    if (lane == 0) s_ek[rsel][wr] = g_qnorm[cand] - 2.f * s;
    __syncthreads();

    // pick 2nd smallest (exact) among the 4 candidates; any one thread per row
    if (wr == 0 && lane == 0) {
        float ek[4];
#pragma unroll
        for (int q = 0; q < 4; q++) ek[q] = s_ek[rsel][q];
        int best = 0;
#pragma unroll
        for (int c = 1; c < 4; c++) if (lex_less(ek[c], is[c], ek[best], is[best])) best = c;
        int sec = (best == 0) ? 1 : 0;
#pragma unroll
        for (int c = 0; c < 4; c++)
            if (c != best && lex_less(ek[c], is[c], ek[sec], is[sec])) sec = c;
        s_nn[rsel] = is[sec];
    }
    __syncthreads();

    // gather: 128 threads per row copy 512 floats (1 float4 each)
    const int nn = s_nn[rsel];
    const int t128 = (wr << 5) | lane;          // 0..127 within the row group
    const float4* src = (const float4*)queue_row(x, qp, nn);
    float4*       dst = (float4*)(out + (size_t)row * DIM);
    dst[t128] = src[t128];
}

// ---------------------------------------------------------------------------
extern "C" void kernel_launch(void* const* d_in, const int* in_sizes, int n_in,
                              void* d_out, int out_size) {
    const float* x   = (const float*)d_in[0];   // (1024, 512)
    const float* qp  = (const float*)d_in[1];   // (32768, 512)
    float*       out = (float*)d_out;           // (1024, 512)

    cudaFuncSetAttribute(mma_top2_kernel,
                         cudaFuncAttributeMaxDynamicSharedMemorySize, SMEM_BYTES);

    // reset prep tickets + slab flags (graph-capturable async memset)
    void* sync_ptr = nullptr;
    cudaGetSymbolAddress(&sync_ptr, g_sync);
    cudaMemsetAsync(sync_ptr, 0, sizeof(int) * (NTILES + 1));

    dim3 grid(NTILES, MTILES);                  // (128, 8) = 1024 CTAs
    mma_top2_kernel<<<grid, 256, SMEM_BYTES>>>(x, qp);

    reduce_rescore_kernel<<<BATCH / 2, 256>>>(x, qp, out);
}

// round 15
// speedup vs baseline: 1.1272x; 1.1272x over previous
#include <cuda_runtime.h>
#include <cuda_fp16.h>
#include <cstdint>

#define BATCH 1024
#define DIM   512
#define QSZ   32768
#define QOFF  (QSZ - BATCH)   // 31744

#define MT 128
#define NT 256
#define KC 64                 // k-chunk
#define NCHUNK (DIM / KC)     // 8
#define NTILES (QSZ / NT)     // 128 CTA col tiles
#define MTILES (BATCH / MT)   // 8
#define PT     (QSZ / 64)     // 512 partial col slabs (one per warp 64-col slab)

#define NSTAGE 2
#define STG_A_BYTES (128 * KC * 2)   // 16384
#define STG_B_BYTES (256 * KC * 2)   // 32768
#define STG_BYTES   (STG_A_BYTES + STG_B_BYTES)   // 49152
#define SMEM_BYTES  (NSTAGE * STG_BYTES)          // 98304

// ---------------------------------------------------------------------------
// helpers
// ---------------------------------------------------------------------------
__device__ __forceinline__ uint32_t smem_to_u32(const void* p) {
    uint32_t a;
    asm("{ .reg .u64 t; cvta.to.shared.u64 t, %1; cvt.u32.u64 %0, t; }" : "=r"(a) : "l"(p));
    return a;
}
__device__ __forceinline__ void cp16(uint32_t saddr, const void* g) {
    asm volatile("cp.async.cg.shared.global [%0], [%1], 16;" :: "r"(saddr), "l"(g));
}
#define CP_COMMIT() asm volatile("cp.async.commit_group;" ::: "memory")
#define CP_WAIT(N)  asm volatile("cp.async.wait_group %0;" :: "n"(N) : "memory")

__device__ __forceinline__ void ldm_x4(uint32_t (&r)[4], uint32_t addr) {
    asm volatile("ldmatrix.sync.aligned.m8n8.x4.shared.b16 {%0,%1,%2,%3}, [%4];"
                 : "=r"(r[0]), "=r"(r[1]), "=r"(r[2]), "=r"(r[3]) : "r"(addr));
}
// m16n8k16, fp16 inputs, fp16 accumulate (C/D = 2 x f16x2 regs)
__device__ __forceinline__ void mma16816h(uint32_t (&c)[2], const uint32_t (&a)[4],
                                          uint32_t b0, uint32_t b1) {
    asm volatile("mma.sync.aligned.m16n8k16.row.col.f16.f16.f16.f16 "
                 "{%0,%1}, {%2,%3,%4,%5}, {%6,%7}, {%0,%1};"
                 : "+r"(c[0]), "+r"(c[1])
                 : "r"(a[0]), "r"(a[1]), "r"(a[2]), "r"(a[3]), "r"(b0), "r"(b1));
}

// swizzled smem byte offset inside a (rows x 64)-fp16 tile (128B rows, 16B chunks)
__device__ __forceinline__ uint32_t swz128(int row, int c8) {
    return (uint32_t)row * 128u + (uint32_t)(((c8) ^ (row & 7)) * 16);
}

struct __align__(16) Top2 { float k1; int i1; float k2; int i2; };

__device__ __align__(16) __half g_qh[(size_t)QSZ * DIM];          // 32 MB fp16 queue
__device__ float g_qnorm[QSZ];
__device__ Top2  g_partial[(size_t)BATCH * PT];                   // 8 MB

__device__ __forceinline__ const float* queue_row(const float* x, const float* qp, int j) {
    return (j < QOFF) ? (qp + (size_t)(j + BATCH) * DIM)
                      : (x  + (size_t)(j - QOFF) * DIM);
}
__device__ __forceinline__ bool lex_less(float ak, int ai, float bk, int bi) {
    return ak < bk || (ak == bk && ai < bi);
}
__device__ __forceinline__ void merge2(float& k1, int& i1, float& k2, int& i2,
                                       float ok1, int oi1, float ok2, int oi2) {
    if (lex_less(ok1, oi1, k1, i1)) {
        if (lex_less(ok2, oi2, k1, i1)) { k2 = ok2; i2 = oi2; }
        else                            { k2 = k1;  i2 = i1;  }
        k1 = ok1; i1 = oi1;
    } else if (lex_less(ok1, oi1, k2, i2)) { k2 = ok1; i2 = oi1; }
}
__device__ __forceinline__ void insert4(float (&ks)[4], int (&is)[4], float k, int i) {
    if (!lex_less(k, i, ks[3], is[3])) return;
    int p = 3;
#pragma unroll
    for (int q = 3; q > 0; q--) {
        if (lex_less(k, i, ks[q-1], is[q-1])) { ks[q] = ks[q-1]; is[q] = is[q-1]; p = q-1; }
    }
    ks[p] = k; is[p] = i;
}

// ---------------------------------------------------------------------------
// Kernel 1: build fp16 queue + exact fp32 qnorm. One warp handles TWO rows;
// all 8 independent 16B loads are issued before any convert/store (MLP=8).
// ---------------------------------------------------------------------------
__global__ void __launch_bounds__(256) prep_kernel(const float* __restrict__ x,
                                                   const float* __restrict__ qp) {
    const int w    = (blockIdx.x * blockDim.x + threadIdx.x) >> 5;  // warp id
    const int lane = threadIdx.x & 31;
    const int r0   = w * 2;
    if (r0 >= QSZ) return;

    const float4* s0 = (const float4*)queue_row(x, qp, r0);
    const float4* s1 = (const float4*)queue_row(x, qp, r0 + 1);

    // issue all 8 loads (4 per row) before any dependent work
    float4 a0 = s0[2 * lane];
    float4 b0 = s0[2 * lane + 1];
    float4 c0 = s0[2 * (lane + 32)];
    float4 d0 = s0[2 * (lane + 32) + 1];
    float4 a1 = s1[2 * lane];
    float4 b1 = s1[2 * lane + 1];
    float4 c1 = s1[2 * (lane + 32)];
    float4 d1 = s1[2 * (lane + 32) + 1];

    uint4* dst0 = (uint4*)(g_qh + (size_t)r0 * DIM);
    uint4* dst1 = (uint4*)(g_qh + (size_t)(r0 + 1) * DIM);

#define PK16(A, B) ({ \
    __half2 _p0 = __floats2half2_rn((A).x, (A).y); \
    __half2 _p1 = __floats2half2_rn((A).z, (A).w); \
    __half2 _p2 = __floats2half2_rn((B).x, (B).y); \
    __half2 _p3 = __floats2half2_rn((B).z, (B).w); \
    uint4 _pk; _pk.x = *(uint32_t*)&_p0; _pk.y = *(uint32_t*)&_p1; \
    _pk.z = *(uint32_t*)&_p2; _pk.w = *(uint32_t*)&_p3; _pk; })

    dst0[lane]      = PK16(a0, b0);
    dst0[lane + 32] = PK16(c0, d0);
    dst1[lane]      = PK16(a1, b1);
    dst1[lane + 32] = PK16(c1, d1);

#define N4(V) fmaf((V).x, (V).x, fmaf((V).y, (V).y, fmaf((V).z, (V).z, (V).w * (V).w)))
    float nrm0 = (N4(a0) + N4(b0)) + (N4(c0) + N4(d0));
    float nrm1 = (N4(a1) + N4(b1)) + (N4(c1) + N4(d1));
#pragma unroll
    for (int o = 16; o; o >>= 1) {
        nrm0 += __shfl_xor_sync(0xffffffffu, nrm0, o);
        nrm1 += __shfl_xor_sync(0xffffffffu, nrm1, o);
    }
    if (lane == 0) { g_qnorm[r0] = nrm0; g_qnorm[r0 + 1] = nrm1; }
}

// ---------------------------------------------------------------------------
// Kernel 2: mma.sync fp16 GEMM (fp16 accumulate), CTA tile 128x256, warp tile
// 64x64, KC=64, 2-stage cp.async ring, 2 CTAs/SM, fused per-row top-2.
// (byte-identical to the R7/R12/R13 kernel)
// ---------------------------------------------------------------------------
__global__ void __launch_bounds__(256, 2) mma_top2_kernel() {
    extern __shared__ __align__(16) char smem[];
    const uint32_t sbase = smem_to_u32(smem);

    const int tid  = threadIdx.x;
    const int wid  = tid >> 5;
    const int lane = tid & 31;
    const int wm   = wid & 1;          // M half (64 rows)
    const int wn   = wid >> 1;         // N quarter (64 cols)
    const int m0   = blockIdx.y * MT;
    const int n0   = blockIdx.x * NT;

    const __half* Ag = g_qh + (size_t)(QOFF + m0) * DIM;  // x rows at queue tail
    const __half* Bg = g_qh + (size_t)n0 * DIM;

    // loaders: A 1024 16B-units (4/thread, row stride 32), B 2048 (8/thread)
    const int rL  = tid >> 3;          // base row 0..31
    const int c8L = tid & 7;           // 16B col group (constant across u)
    const uint32_t soL = swz128(rL, c8L);   // +u*4096 for row+32u (32u % 8 == 0)

#define LOAD_CHUNK(ck, stg) do { \
    uint32_t _sA = sbase + (uint32_t)(stg) * STG_BYTES; \
    uint32_t _sB = _sA + STG_A_BYTES; \
    int _ko = (ck) * KC + c8L * 8; \
    _Pragma("unroll") \
    for (int _u = 0; _u < 4; _u++) \
        cp16(_sA + soL + _u * 4096u, Ag + (size_t)(rL + 32 * _u) * DIM + _ko); \
    _Pragma("unroll") \
    for (int _u = 0; _u < 8; _u++) \
        cp16(_sB + soL + _u * 4096u, Bg + (size_t)(rL + 32 * _u) * DIM + _ko); \
    CP_COMMIT(); \
} while (0)

    // fragment addressing
    const int arow_lo = wm * 64 + (lane & 15);
    const int ac8_lo  = (lane >> 4);
    const int bg      = lane >> 3;
    const int brow_lo = wn * 64 + (bg >> 1) * 8 + (lane & 7);
    const int bc8_lo  = (bg & 1);

    uint32_t acc[4][8][2] = {};
    uint32_t af[4][4], bf[4][4];

    LOAD_CHUNK(0, 0);
    LOAD_CHUNK(1, 1);

    for (int c = 0; c < NCHUNK; c++) {
        const int stg = c & 1;
        CP_WAIT(1);
        __syncthreads();

        const uint32_t sA = sbase + (uint32_t)stg * STG_BYTES;
        const uint32_t sB = sA + STG_A_BYTES;

#pragma unroll
        for (int ks = 0; ks < 4; ks++) {
#pragma unroll
            for (int a = 0; a < 4; a++)
                ldm_x4(af[a], sA + swz128(arow_lo + a * 16, ks * 2 + ac8_lo));
#pragma unroll
            for (int b2 = 0; b2 < 4; b2++)
                ldm_x4(bf[b2], sB + swz128(brow_lo + b2 * 16, ks * 2 + bc8_lo));
#pragma unroll
            for (int a = 0; a < 4; a++)
#pragma unroll
                for (int b = 0; b < 8; b++)
                    mma16816h(acc[a][b], af[a], bf[b >> 1][(b & 1) * 2],
                                                bf[b >> 1][(b & 1) * 2 + 1]);
        }
        __syncthreads();   // all warps done reading stage before it is reloaded
        if (c + 2 < NCHUNK) LOAD_CHUNK(c + 2, stg);
    }

    // Epilogue: keys = qnorm[j] - 2*S; per-row top-2 over this warp's 64 cols.
    const int gid = lane >> 2, tig = lane & 3;
    const float INF = __int_as_float(0x7f800000);

    float qn[8][2];
#pragma unroll
    for (int b = 0; b < 8; b++) {
        int j = n0 + wn * 64 + b * 8 + tig * 2;
        qn[b][0] = g_qnorm[j];
        qn[b][1] = g_qnorm[j + 1];
    }

    float k1[8], k2[8]; int i1[8], i2[8];
#pragma unroll
    for (int s = 0; s < 8; s++) { k1[s] = k2[s] = INF; i1[s] = i2[s] = 0x7fffffff; }

#pragma unroll
    for (int a = 0; a < 4; a++)
#pragma unroll
        for (int b = 0; b < 8; b++) {
            int j = n0 + wn * 64 + b * 8 + tig * 2;
#pragma unroll
            for (int h = 0; h < 2; h++) {       // h=0: row gid, h=1: row gid+8
                int s = a * 2 + h;
                float2 v = __half22float2(*(const __half2*)&acc[a][b][h]);
#pragma unroll
                for (int e = 0; e < 2; e++) {
                    float key = fmaf(-2.f, e ? v.y : v.x, qn[b][e]);
                    int   jj  = j + e;
                    if (lex_less(key, jj, k1[s], i1[s])) {
                        k2[s] = k1[s]; i2[s] = i1[s]; k1[s] = key; i1[s] = jj;
                    } else if (lex_less(key, jj, k2[s], i2[s])) { k2[s] = key; i2[s] = jj; }
                }
            }
        }

#pragma unroll
    for (int off = 1; off <= 2; off <<= 1) {
#pragma unroll
        for (int s = 0; s < 8; s++) {
            float ok1 = __shfl_xor_sync(0xffffffffu, k1[s], off);
            int   oi1 = __shfl_xor_sync(0xffffffffu, i1[s], off);
            float ok2 = __shfl_xor_sync(0xffffffffu, k2[s], off);
            int   oi2 = __shfl_xor_sync(0xffffffffu, i2[s], off);
            merge2(k1[s], i1[s], k2[s], i2[s], ok1, oi1, ok2, oi2);
        }
    }

    if (tig == 0) {
        int ct = blockIdx.x * 4 + wn;
#pragma unroll
        for (int s = 0; s < 8; s++) {
            int row = m0 + wm * 64 + (s >> 1) * 16 + (s & 1) * 8 + gid;
            Top2 t; t.k1 = k1[s]; t.i1 = i1[s]; t.k2 = k2[s]; t.i2 = i2[s];
            g_partial[(size_t)row * PT + ct] = t;
        }
    }
}

// ---------------------------------------------------------------------------
// Kernel 3: 2 rows per 256-thread block (4 warps per row). Each warp loads
// 128 partials -> warp top-4; cross-warp merge in smem; the 4 warps rescore
// one candidate each (exact fp32); pick 2nd smallest; gather the queue row.
// (byte-identical to R12/R13)
// ---------------------------------------------------------------------------
__global__ void __launch_bounds__(256) reduce_rescore_kernel(const float* __restrict__ x,
                                                             const float* __restrict__ qp,
                                                             float* __restrict__ out) {
    const int tid  = threadIdx.x;
    const int wid  = tid >> 5;
    const int lane = tid & 31;
    const int rsel = wid >> 2;                 // 0/1: which of the 2 rows
    const int wr   = wid & 3;                  // warp-within-row 0..3
    const int row  = blockIdx.x * 2 + rsel;
    const float INF = __int_as_float(0x7f800000);

    __shared__ float s_k[2][4][4];
    __shared__ int   s_i[2][4][4];
    __shared__ float s_ek[2][4];
    __shared__ int   s_nn[2];

    float ks[4]; int is[4];
#pragma unroll
    for (int q = 0; q < 4; q++) { ks[q] = INF; is[q] = 0x7fffffff; }

    // each warp covers 128 consecutive partial slots
    const Top2* p = g_partial + (size_t)row * PT + wr * 128;
#pragma unroll
    for (int t = 0; t < 4; t++) {
        Top2 o = p[lane + t * 32];
        insert4(ks, is, o.k1, o.i1);
        insert4(ks, is, o.k2, o.i2);
    }
#pragma unroll
    for (int off = 16; off; off >>= 1) {
        float ok[4]; int oi[4];
#pragma unroll
        for (int q = 0; q < 4; q++) {
            ok[q] = __shfl_xor_sync(0xffffffffu, ks[q], off);
            oi[q] = __shfl_xor_sync(0xffffffffu, is[q], off);
        }
#pragma unroll
        for (int q = 0; q < 4; q++) insert4(ks, is, ok[q], oi[q]);
    }
    if (lane < 4) { s_k[rsel][wr][lane] = ks[lane]; s_i[rsel][wr][lane] = is[lane]; }
    __syncthreads();

    // every warp recomputes the row's global top-4 from the 16 smem entries
#pragma unroll
    for (int q = 0; q < 4; q++) { ks[q] = INF; is[q] = 0x7fffffff; }
#pragma unroll
    for (int w4 = 0; w4 < 4; w4++)
#pragma unroll
        for (int q = 0; q < 4; q++)
            insert4(ks, is, s_k[rsel][w4][q], s_i[rsel][w4][q]);

    // warp wr rescores candidate wr (exact fp32 dot over 512 dims)
    const int cand = is[wr];
    const float* xr = x + (size_t)row * DIM;
    const float* qr = queue_row(x, qp, cand);
    float s = 0.f;
#pragma unroll
    for (int kk = 0; kk < 4; kk++) {
        int k = (lane + 32 * kk) * 4;
        float4 a = *(const float4*)(xr + k);
        float4 b = *(const float4*)(qr + k);
        s += a.x * b.x + a.y * b.y + a.z * b.z + a.w * b.w;
    }
#pragma unroll
    for (int o = 16; o; o >>= 1) s += __shfl_xor_sync(0xffffffffu, s, o);
    if (lane == 0) s_ek[rsel][wr] = g_qnorm[cand] - 2.f * s;
    __syncthreads();

    // pick 2nd smallest (exact) among the 4 candidates; any one thread per row
    if (wr == 0 && lane == 0) {
        float ek[4];
#pragma unroll
        for (int q = 0; q < 4; q++) ek[q] = s_ek[rsel][q];
        int best = 0;
#pragma unroll
        for (int c = 1; c < 4; c++) if (lex_less(ek[c], is[c], ek[best], is[best])) best = c;
        int sec = (best == 0) ? 1 : 0;
#pragma unroll
        for (int c = 0; c < 4; c++)
            if (c != best && lex_less(ek[c], is[c], ek[sec], is[sec])) sec = c;
        s_nn[rsel] = is[sec];
    }
    __syncthreads();

    // gather: 128 threads per row copy 512 floats (1 float4 each)
    const int nn = s_nn[rsel];
    const int t128 = (wr << 5) | lane;          // 0..127 within the row group
    const float4* src = (const float4*)queue_row(x, qp, nn);
    float4*       dst = (float4*)(out + (size_t)row * DIM);
    dst[t128] = src[t128];
}

// ---------------------------------------------------------------------------
extern "C" void kernel_launch(void* const* d_in, const int* in_sizes, int n_in,
                              void* d_out, int out_size) {
    const float* x   = (const float*)d_in[0];   // (1024, 512)
    const float* qp  = (const float*)d_in[1];   // (32768, 512)
    float*       out = (float*)d_out;           // (1024, 512)

    cudaFuncSetAttribute(mma_top2_kernel,
                         cudaFuncAttributeMaxDynamicSharedMemorySize, SMEM_BYTES);

    prep_kernel<<<QSZ / 16, 256>>>(x, qp);      // 2 rows per warp

    dim3 grid(NTILES, MTILES);                  // (128, 8) = 1024 CTAs
    mma_top2_kernel<<<grid, 256, SMEM_BYTES>>>();

    reduce_rescore_kernel<<<BATCH / 2, 256>>>(x, qp, out);
}

// round 16
// speedup vs baseline: 1.1396x; 1.0110x over previous
#include <cuda_runtime.h>
#include <cuda_fp16.h>
#include <cstdint>

#define BATCH 1024
#define DIM   512
#define QSZ   32768
#define QOFF  (QSZ - BATCH)   // 31744

#define MT 128
#define NT 256
#define KC 64                 // k-chunk
#define NCHUNK (DIM / KC)     // 8
#define NTILES (QSZ / NT)     // 128 CTA col tiles
#define MTILES (BATCH / MT)   // 8
#define PT     (QSZ / 64)     // 512 partial col slabs (one per warp 64-col slab)

#define NSTAGE 2
#define STG_A_BYTES (128 * KC * 2)   // 16384
#define STG_B_BYTES (256 * KC * 2)   // 32768
#define STG_BYTES   (STG_A_BYTES + STG_B_BYTES)   // 49152
#define SMEM_BYTES  (NSTAGE * STG_BYTES)          // 98304

// ---------------------------------------------------------------------------
// helpers
// ---------------------------------------------------------------------------
__device__ __forceinline__ uint32_t smem_to_u32(const void* p) {
    uint32_t a;
    asm("{ .reg .u64 t; cvta.to.shared.u64 t, %1; cvt.u32.u64 %0, t; }" : "=r"(a) : "l"(p));
    return a;
}
__device__ __forceinline__ void cp16(uint32_t saddr, const void* g) {
    asm volatile("cp.async.cg.shared.global [%0], [%1], 16;" :: "r"(saddr), "l"(g));
}
#define CP_COMMIT() asm volatile("cp.async.commit_group;" ::: "memory")
#define CP_WAIT(N)  asm volatile("cp.async.wait_group %0;" :: "n"(N) : "memory")

__device__ __forceinline__ void ldm_x4(uint32_t (&r)[4], uint32_t addr) {
    asm volatile("ldmatrix.sync.aligned.m8n8.x4.shared.b16 {%0,%1,%2,%3}, [%4];"
                 : "=r"(r[0]), "=r"(r[1]), "=r"(r[2]), "=r"(r[3]) : "r"(addr));
}
// m16n8k16, fp16 inputs, fp16 accumulate (C/D = 2 x f16x2 regs)
__device__ __forceinline__ void mma16816h(uint32_t (&c)[2], const uint32_t (&a)[4],
                                          uint32_t b0, uint32_t b1) {
    asm volatile("mma.sync.aligned.m16n8k16.row.col.f16.f16.f16.f16 "
                 "{%0,%1}, {%2,%3,%4,%5}, {%6,%7}, {%0,%1};"
                 : "+r"(c[0]), "+r"(c[1])
                 : "r"(a[0]), "r"(a[1]), "r"(a[2]), "r"(a[3]), "r"(b0), "r"(b1));
}

// swizzled smem byte offset inside a (rows x 64)-fp16 tile (128B rows, 16B chunks)
__device__ __forceinline__ uint32_t swz128(int row, int c8) {
    return (uint32_t)row * 128u + (uint32_t)(((c8) ^ (row & 7)) * 16);
}

struct __align__(16) Top2 { float k1; int i1; float k2; int i2; };

__device__ __align__(16) __half g_qh[(size_t)QSZ * DIM];          // 32 MB fp16 queue
__device__ float g_qnorm[QSZ];
__device__ Top2  g_partial[(size_t)BATCH * PT];                   // 8 MB

__device__ __forceinline__ const float* queue_row(const float* x, const float* qp, int j) {
    return (j < QOFF) ? (qp + (size_t)(j + BATCH) * DIM)
                      : (x  + (size_t)(j - QOFF) * DIM);
}
__device__ __forceinline__ bool lex_less(float ak, int ai, float bk, int bi) {
    return ak < bk || (ak == bk && ai < bi);
}
__device__ __forceinline__ void merge2(float& k1, int& i1, float& k2, int& i2,
                                       float ok1, int oi1, float ok2, int oi2) {
    if (lex_less(ok1, oi1, k1, i1)) {
        if (lex_less(ok2, oi2, k1, i1)) { k2 = ok2; i2 = oi2; }
        else                            { k2 = k1;  i2 = i1;  }
        k1 = ok1; i1 = oi1;
    } else if (lex_less(ok1, oi1, k2, i2)) { k2 = ok1; i2 = oi1; }
}
__device__ __forceinline__ void insert4(float (&ks)[4], int (&is)[4], float k, int i) {
    if (!lex_less(k, i, ks[3], is[3])) return;
    int p = 3;
#pragma unroll
    for (int q = 3; q > 0; q--) {
        if (lex_less(k, i, ks[q-1], is[q-1])) { ks[q] = ks[q-1]; is[q] = is[q-1]; p = q-1; }
    }
    ks[p] = k; is[p] = i;
}

// ---------------------------------------------------------------------------
// Kernel 1: build fp16 queue + exact fp32 qnorm. 1 warp / row.
// Each lane: 16 consecutive floats -> two float4 loads, one uint4 (16B) store.
// Norm kept in 4 independent partials to break the FMA dependence chain.
// ---------------------------------------------------------------------------
__global__ void __launch_bounds__(256) prep_kernel(const float* __restrict__ x,
                                                   const float* __restrict__ qp) {
    int w    = (blockIdx.x * blockDim.x + threadIdx.x) >> 5;
    int lane = threadIdx.x & 31;
    if (w >= QSZ) return;
    const float4* s4 = (const float4*)queue_row(x, qp, w);
    uint4* dst = (uint4*)(g_qh + (size_t)w * DIM);

    float n0 = 0.f, n1 = 0.f, n2 = 0.f, n3 = 0.f;
#pragma unroll
    for (int i = 0; i < 2; i++) {
        float4 a = s4[2 * (lane + 32 * i)];
        float4 b = s4[2 * (lane + 32 * i) + 1];
        n0 = fmaf(a.x, a.x, fmaf(a.y, a.y, n0));
        n1 = fmaf(a.z, a.z, fmaf(a.w, a.w, n1));
        n2 = fmaf(b.x, b.x, fmaf(b.y, b.y, n2));
        n3 = fmaf(b.z, b.z, fmaf(b.w, b.w, n3));
        __half2 p0 = __floats2half2_rn(a.x, a.y);
        __half2 p1 = __floats2half2_rn(a.z, a.w);
        __half2 p2 = __floats2half2_rn(b.x, b.y);
        __half2 p3 = __floats2half2_rn(b.z, b.w);
        uint4 pk;
        pk.x = *(uint32_t*)&p0; pk.y = *(uint32_t*)&p1;
        pk.z = *(uint32_t*)&p2; pk.w = *(uint32_t*)&p3;
        dst[lane + 32 * i] = pk;
    }
    float nrm = (n0 + n1) + (n2 + n3);
#pragma unroll
    for (int o = 16; o; o >>= 1) nrm += __shfl_xor_sync(0xffffffffu, nrm, o);
    if (lane == 0) g_qnorm[w] = nrm;
}

// ---------------------------------------------------------------------------
// Kernel 2: mma.sync fp16 GEMM (fp16 accumulate), CTA tile 128x256, warp tile
// 64x64, KC=64, 2-stage cp.async ring, 2 CTAs/SM, fused per-row top-2.
// (byte-identical to the R7/R12/R13 kernel)
// ---------------------------------------------------------------------------
__global__ void __launch_bounds__(256, 2) mma_top2_kernel() {
    extern __shared__ __align__(16) char smem[];
    const uint32_t sbase = smem_to_u32(smem);

    const int tid  = threadIdx.x;
    const int wid  = tid >> 5;
    const int lane = tid & 31;
    const int wm   = wid & 1;          // M half (64 rows)
    const int wn   = wid >> 1;         // N quarter (64 cols)
    const int m0   = blockIdx.y * MT;
    const int n0   = blockIdx.x * NT;

    const __half* Ag = g_qh + (size_t)(QOFF + m0) * DIM;  // x rows at queue tail
    const __half* Bg = g_qh + (size_t)n0 * DIM;

    // loaders: A 1024 16B-units (4/thread, row stride 32), B 2048 (8/thread)
    const int rL  = tid >> 3;          // base row 0..31
    const int c8L = tid & 7;           // 16B col group (constant across u)
    const uint32_t soL = swz128(rL, c8L);   // +u*4096 for row+32u (32u % 8 == 0)

#define LOAD_CHUNK(ck, stg) do { \
    uint32_t _sA = sbase + (uint32_t)(stg) * STG_BYTES; \
    uint32_t _sB = _sA + STG_A_BYTES; \
    int _ko = (ck) * KC + c8L * 8; \
    _Pragma("unroll") \
    for (int _u = 0; _u < 4; _u++) \
        cp16(_sA + soL + _u * 4096u, Ag + (size_t)(rL + 32 * _u) * DIM + _ko); \
    _Pragma("unroll") \
    for (int _u = 0; _u < 8; _u++) \
        cp16(_sB + soL + _u * 4096u, Bg + (size_t)(rL + 32 * _u) * DIM + _ko); \
    CP_COMMIT(); \
} while (0)

    // fragment addressing
    const int arow_lo = wm * 64 + (lane & 15);
    const int ac8_lo  = (lane >> 4);
    const int bg      = lane >> 3;
    const int brow_lo = wn * 64 + (bg >> 1) * 8 + (lane & 7);
    const int bc8_lo  = (bg & 1);

    uint32_t acc[4][8][2] = {};
    uint32_t af[4][4], bf[4][4];

    LOAD_CHUNK(0, 0);
    LOAD_CHUNK(1, 1);

    for (int c = 0; c < NCHUNK; c++) {
        const int stg = c & 1;
        CP_WAIT(1);
        __syncthreads();

        const uint32_t sA = sbase + (uint32_t)stg * STG_BYTES;
        const uint32_t sB = sA + STG_A_BYTES;

#pragma unroll
        for (int ks = 0; ks < 4; ks++) {
#pragma unroll
            for (int a = 0; a < 4; a++)
                ldm_x4(af[a], sA + swz128(arow_lo + a * 16, ks * 2 + ac8_lo));
#pragma unroll
            for (int b2 = 0; b2 < 4; b2++)
                ldm_x4(bf[b2], sB + swz128(brow_lo + b2 * 16, ks * 2 + bc8_lo));
#pragma unroll
            for (int a = 0; a < 4; a++)
#pragma unroll
                for (int b = 0; b < 8; b++)
                    mma16816h(acc[a][b], af[a], bf[b >> 1][(b & 1) * 2],
                                                bf[b >> 1][(b & 1) * 2 + 1]);
        }
        __syncthreads();   // all warps done reading stage before it is reloaded
        if (c + 2 < NCHUNK) LOAD_CHUNK(c + 2, stg);
    }

    // Epilogue: keys = qnorm[j] - 2*S; per-row top-2 over this warp's 64 cols.
    const int gid = lane >> 2, tig = lane & 3;
    const float INF = __int_as_float(0x7f800000);

    float qn[8][2];
#pragma unroll
    for (int b = 0; b < 8; b++) {
        int j = n0 + wn * 64 + b * 8 + tig * 2;
        qn[b][0] = g_qnorm[j];
        qn[b][1] = g_qnorm[j + 1];
    }

    float k1[8], k2[8]; int i1[8], i2[8];
#pragma unroll
    for (int s = 0; s < 8; s++) { k1[s] = k2[s] = INF; i1[s] = i2[s] = 0x7fffffff; }

#pragma unroll
    for (int a = 0; a < 4; a++)
#pragma unroll
        for (int b = 0; b < 8; b++) {
            int j = n0 + wn * 64 + b * 8 + tig * 2;
#pragma unroll
            for (int h = 0; h < 2; h++) {       // h=0: row gid, h=1: row gid+8
                int s = a * 2 + h;
                float2 v = __half22float2(*(const __half2*)&acc[a][b][h]);
#pragma unroll
                for (int e = 0; e < 2; e++) {
                    float key = fmaf(-2.f, e ? v.y : v.x, qn[b][e]);
                    int   jj  = j + e;
                    if (lex_less(key, jj, k1[s], i1[s])) {
                        k2[s] = k1[s]; i2[s] = i1[s]; k1[s] = key; i1[s] = jj;
                    } else if (lex_less(key, jj, k2[s], i2[s])) { k2[s] = key; i2[s] = jj; }
                }
            }
        }

#pragma unroll
    for (int off = 1; off <= 2; off <<= 1) {
#pragma unroll
        for (int s = 0; s < 8; s++) {
            float ok1 = __shfl_xor_sync(0xffffffffu, k1[s], off);
            int   oi1 = __shfl_xor_sync(0xffffffffu, i1[s], off);
            float ok2 = __shfl_xor_sync(0xffffffffu, k2[s], off);
            int   oi2 = __shfl_xor_sync(0xffffffffu, i2[s], off);
            merge2(k1[s], i1[s], k2[s], i2[s], ok1, oi1, ok2, oi2);
        }
    }

    if (tig == 0) {
        int ct = blockIdx.x * 4 + wn;
#pragma unroll
        for (int s = 0; s < 8; s++) {
            int row = m0 + wm * 64 + (s >> 1) * 16 + (s & 1) * 8 + gid;
            Top2 t; t.k1 = k1[s]; t.i1 = i1[s]; t.k2 = k2[s]; t.i2 = i2[s];
            g_partial[(size_t)row * PT + ct] = t;
        }
    }
}

// ---------------------------------------------------------------------------
// Kernel 3: 2 rows per 256-thread block (4 warps per row). Each warp loads
// 128 partials -> warp top-4; cross-warp merge in smem; the 4 warps rescore
// one candidate each (exact fp32); pick 2nd smallest; gather the queue row.
// (byte-identical to R12/R13)
// ---------------------------------------------------------------------------
__global__ void __launch_bounds__(256) reduce_rescore_kernel(const float* __restrict__ x,
                                                             const float* __restrict__ qp,
                                                             float* __restrict__ out) {
    const int tid  = threadIdx.x;
    const int wid  = tid >> 5;
    const int lane = tid & 31;
    const int rsel = wid >> 2;                 // 0/1: which of the 2 rows
    const int wr   = wid & 3;                  // warp-within-row 0..3
    const int row  = blockIdx.x * 2 + rsel;
    const float INF = __int_as_float(0x7f800000);

    __shared__ float s_k[2][4][4];
    __shared__ int   s_i[2][4][4];
    __shared__ float s_ek[2][4];
    __shared__ int   s_nn[2];

    float ks[4]; int is[4];
#pragma unroll
    for (int q = 0; q < 4; q++) { ks[q] = INF; is[q] = 0x7fffffff; }

    // each warp covers 128 consecutive partial slots
    const Top2* p = g_partial + (size_t)row * PT + wr * 128;
#pragma unroll
    for (int t = 0; t < 4; t++) {
        Top2 o = p[lane + t * 32];
        insert4(ks, is, o.k1, o.i1);
        insert4(ks, is, o.k2, o.i2);
    }
#pragma unroll
    for (int off = 16; off; off >>= 1) {
        float ok[4]; int oi[4];
#pragma unroll
        for (int q = 0; q < 4; q++) {
            ok[q] = __shfl_xor_sync(0xffffffffu, ks[q], off);
            oi[q] = __shfl_xor_sync(0xffffffffu, is[q], off);
        }
#pragma unroll
        for (int q = 0; q < 4; q++) insert4(ks, is, ok[q], oi[q]);
    }
    if (lane < 4) { s_k[rsel][wr][lane] = ks[lane]; s_i[rsel][wr][lane] = is[lane]; }
    __syncthreads();

    // every warp recomputes the row's global top-4 from the 16 smem entries
#pragma unroll
    for (int q = 0; q < 4; q++) { ks[q] = INF; is[q] = 0x7fffffff; }
#pragma unroll
    for (int w4 = 0; w4 < 4; w4++)
#pragma unroll
        for (int q = 0; q < 4; q++)
            insert4(ks, is, s_k[rsel][w4][q], s_i[rsel][w4][q]);

    // warp wr rescores candidate wr (exact fp32 dot over 512 dims)
    const int cand = is[wr];
    const float* xr = x + (size_t)row * DIM;
    const float* qr = queue_row(x, qp, cand);
    float s = 0.f;
#pragma unroll
    for (int kk = 0; kk < 4; kk++) {
        int k = (lane + 32 * kk) * 4;
        float4 a = *(const float4*)(xr + k);
        float4 b = *(const float4*)(qr + k);
        s += a.x * b.x + a.y * b.y + a.z * b.z + a.w * b.w;
    }
#pragma unroll
    for (int o = 16; o; o >>= 1) s += __shfl_xor_sync(0xffffffffu, s, o);
    if (lane == 0) s_ek[rsel][wr] = g_qnorm[cand] - 2.f * s;
    __syncthreads();

    // pick 2nd smallest (exact) among the 4 candidates; any one thread per row
    if (wr == 0 && lane == 0) {
        float ek[4];
#pragma unroll
        for (int q = 0; q < 4; q++) ek[q] = s_ek[rsel][q];
        int best = 0;
#pragma unroll
        for (int c = 1; c < 4; c++) if (lex_less(ek[c], is[c], ek[best], is[best])) best = c;
        int sec = (best == 0) ? 1 : 0;
#pragma unroll
        for (int c = 0; c < 4; c++)
            if (c != best && lex_less(ek[c], is[c], ek[sec], is[sec])) sec = c;
        s_nn[rsel] = is[sec];
    }
    __syncthreads();

    // gather: 128 threads per row copy 512 floats (1 float4 each)
    const int nn = s_nn[rsel];
    const int t128 = (wr << 5) | lane;          // 0..127 within the row group
    const float4* src = (const float4*)queue_row(x, qp, nn);
    float4*       dst = (float4*)(out + (size_t)row * DIM);
    dst[t128] = src[t128];
}

// ---------------------------------------------------------------------------
extern "C" void kernel_launch(void* const* d_in, const int* in_sizes, int n_in,
                              void* d_out, int out_size) {
    const float* x   = (const float*)d_in[0];   // (1024, 512)
    const float* qp  = (const float*)d_in[1];   // (32768, 512)
    float*       out = (float*)d_out;           // (1024, 512)

    cudaFuncSetAttribute(mma_top2_kernel,
                         cudaFuncAttributeMaxDynamicSharedMemorySize, SMEM_BYTES);

    prep_kernel<<<QSZ / 8, 256>>>(x, qp);

    dim3 grid(NTILES, MTILES);                  // (128, 8) = 1024 CTAs
    mma_top2_kernel<<<grid, 256, SMEM_BYTES>>>();

    reduce_rescore_kernel<<<BATCH / 2, 256>>>(x, qp, out);
}

// round 17
// speedup vs baseline: 1.1513x; 1.0102x over previous
#include <cuda_runtime.h>
#include <cuda_fp16.h>
#include <cstdint>

#define BATCH 1024
#define DIM   512
#define QSZ   32768
#define QOFF  (QSZ - BATCH)   // 31744

#define MT 128
#define NT 256
#define KC 64                 // k-chunk
#define NCHUNK (DIM / KC)     // 8
#define NTILES (QSZ / NT)     // 128 CTA col tiles
#define MTILES (BATCH / MT)   // 8
#define PT     (QSZ / 64)     // 512 partial col slabs (one per warp 64-col slab)

#define NSTAGE 2
#define STG_A_BYTES (128 * KC * 2)   // 16384
#define STG_B_BYTES (256 * KC * 2)   // 32768
#define STG_BYTES   (STG_A_BYTES + STG_B_BYTES)   // 49152
#define SMEM_BYTES  (NSTAGE * STG_BYTES)          // 98304

// ---------------------------------------------------------------------------
// helpers
// ---------------------------------------------------------------------------
__device__ __forceinline__ uint32_t smem_to_u32(const void* p) {
    uint32_t a;
    asm("{ .reg .u64 t; cvta.to.shared.u64 t, %1; cvt.u32.u64 %0, t; }" : "=r"(a) : "l"(p));
    return a;
}
__device__ __forceinline__ void cp16(uint32_t saddr, const void* g) {
    asm volatile("cp.async.cg.shared.global [%0], [%1], 16;" :: "r"(saddr), "l"(g));
}
#define CP_COMMIT() asm volatile("cp.async.commit_group;" ::: "memory")
#define CP_WAIT(N)  asm volatile("cp.async.wait_group %0;" :: "n"(N) : "memory")

__device__ __forceinline__ void ldm_x4(uint32_t (&r)[4], uint32_t addr) {
    asm volatile("ldmatrix.sync.aligned.m8n8.x4.shared.b16 {%0,%1,%2,%3}, [%4];"
                 : "=r"(r[0]), "=r"(r[1]), "=r"(r[2]), "=r"(r[3]) : "r"(addr));
}
// m16n8k16, fp16 inputs, fp16 accumulate (C/D = 2 x f16x2 regs)
__device__ __forceinline__ void mma16816h(uint32_t (&c)[2], const uint32_t (&a)[4],
                                          uint32_t b0, uint32_t b1) {
    asm volatile("mma.sync.aligned.m16n8k16.row.col.f16.f16.f16.f16 "
                 "{%0,%1}, {%2,%3,%4,%5}, {%6,%7}, {%0,%1};"
                 : "+r"(c[0]), "+r"(c[1])
                 : "r"(a[0]), "r"(a[1]), "r"(a[2]), "r"(a[3]), "r"(b0), "r"(b1));
}

// swizzled smem byte offset inside a (rows x 64)-fp16 tile (128B rows, 16B chunks)
__device__ __forceinline__ uint32_t swz128(int row, int c8) {
    return (uint32_t)row * 128u + (uint32_t)(((c8) ^ (row & 7)) * 16);
}

struct __align__(16) Top2 { float k1; int i1; float k2; int i2; };

__device__ __align__(16) __half g_qh[(size_t)QSZ * DIM];          // 32 MB fp16 queue
__device__ float g_qnorm[QSZ];
__device__ Top2  g_partial[(size_t)BATCH * PT];                   // 8 MB

__device__ __forceinline__ const float* queue_row(const float* x, const float* qp, int j) {
    return (j < QOFF) ? (qp + (size_t)(j + BATCH) * DIM)
                      : (x  + (size_t)(j - QOFF) * DIM);
}
__device__ __forceinline__ bool lex_less(float ak, int ai, float bk, int bi) {
    return ak < bk || (ak == bk && ai < bi);
}
__device__ __forceinline__ void merge2(float& k1, int& i1, float& k2, int& i2,
                                       float ok1, int oi1, float ok2, int oi2) {
    if (lex_less(ok1, oi1, k1, i1)) {
        if (lex_less(ok2, oi2, k1, i1)) { k2 = ok2; i2 = oi2; }
        else                            { k2 = k1;  i2 = i1;  }
        k1 = ok1; i1 = oi1;
    } else if (lex_less(ok1, oi1, k2, i2)) { k2 = ok1; i2 = oi1; }
}
__device__ __forceinline__ void insert4(float (&ks)[4], int (&is)[4], float k, int i) {
    if (!lex_less(k, i, ks[3], is[3])) return;
    int p = 3;
#pragma unroll
    for (int q = 3; q > 0; q--) {
        if (lex_less(k, i, ks[q-1], is[q-1])) { ks[q] = ks[q-1]; is[q] = is[q-1]; p = q-1; }
    }
    ks[p] = k; is[p] = i;
}

// ---------------------------------------------------------------------------
// Kernel 1: build fp16 queue + exact fp32 qnorm. 1 warp / row.
// fp32 source reads use streaming (evict-first) hint: read-once data must not
// displace the fp16 queue the GEMM will re-read ~8x from L2.
// ---------------------------------------------------------------------------
__global__ void __launch_bounds__(256) prep_kernel(const float* __restrict__ x,
                                                   const float* __restrict__ qp) {
    int w    = (blockIdx.x * blockDim.x + threadIdx.x) >> 5;
    int lane = threadIdx.x & 31;
    if (w >= QSZ) return;
    const float4* s4 = (const float4*)queue_row(x, qp, w);
    uint4* dst = (uint4*)(g_qh + (size_t)w * DIM);

    float n0 = 0.f, n1 = 0.f, n2 = 0.f, n3 = 0.f;
#pragma unroll
    for (int i = 0; i < 2; i++) {
        float4 a = __ldcs(&s4[2 * (lane + 32 * i)]);
        float4 b = __ldcs(&s4[2 * (lane + 32 * i) + 1]);
        n0 = fmaf(a.x, a.x, fmaf(a.y, a.y, n0));
        n1 = fmaf(a.z, a.z, fmaf(a.w, a.w, n1));
        n2 = fmaf(b.x, b.x, fmaf(b.y, b.y, n2));
        n3 = fmaf(b.z, b.z, fmaf(b.w, b.w, n3));
        __half2 p0 = __floats2half2_rn(a.x, a.y);
        __half2 p1 = __floats2half2_rn(a.z, a.w);
        __half2 p2 = __floats2half2_rn(b.x, b.y);
        __half2 p3 = __floats2half2_rn(b.z, b.w);
        uint4 pk;
        pk.x = *(uint32_t*)&p0; pk.y = *(uint32_t*)&p1;
        pk.z = *(uint32_t*)&p2; pk.w = *(uint32_t*)&p3;
        dst[lane + 32 * i] = pk;
    }
    float nrm = (n0 + n1) + (n2 + n3);
#pragma unroll
    for (int o = 16; o; o >>= 1) nrm += __shfl_xor_sync(0xffffffffu, nrm, o);
    if (lane == 0) g_qnorm[w] = nrm;
}

// ---------------------------------------------------------------------------
// Kernel 2: mma.sync fp16 GEMM (fp16 accumulate), CTA tile 128x256, warp tile
// 64x64, KC=64, 2-stage cp.async ring, 2 CTAs/SM, fused per-row top-2.
// (byte-identical to the R7/R12/R13 kernel)
// ---------------------------------------------------------------------------
__global__ void __launch_bounds__(256, 2) mma_top2_kernel() {
    extern __shared__ __align__(16) char smem[];
    const uint32_t sbase = smem_to_u32(smem);

    const int tid  = threadIdx.x;
    const int wid  = tid >> 5;
    const int lane = tid & 31;
    const int wm   = wid & 1;          // M half (64 rows)
    const int wn   = wid >> 1;         // N quarter (64 cols)
    const int m0   = blockIdx.y * MT;
    const int n0   = blockIdx.x * NT;

    const __half* Ag = g_qh + (size_t)(QOFF + m0) * DIM;  // x rows at queue tail
    const __half* Bg = g_qh + (size_t)n0 * DIM;

    // loaders: A 1024 16B-units (4/thread, row stride 32), B 2048 (8/thread)
    const int rL  = tid >> 3;          // base row 0..31
    const int c8L = tid & 7;           // 16B col group (constant across u)
    const uint32_t soL = swz128(rL, c8L);   // +u*4096 for row+32u (32u % 8 == 0)

#define LOAD_CHUNK(ck, stg) do { \
    uint32_t _sA = sbase + (uint32_t)(stg) * STG_BYTES; \
    uint32_t _sB = _sA + STG_A_BYTES; \
    int _ko = (ck) * KC + c8L * 8; \
    _Pragma("unroll") \
    for (int _u = 0; _u < 4; _u++) \
        cp16(_sA + soL + _u * 4096u, Ag + (size_t)(rL + 32 * _u) * DIM + _ko); \
    _Pragma("unroll") \
    for (int _u = 0; _u < 8; _u++) \
        cp16(_sB + soL + _u * 4096u, Bg + (size_t)(rL + 32 * _u) * DIM + _ko); \
    CP_COMMIT(); \
} while (0)

    // fragment addressing
    const int arow_lo = wm * 64 + (lane & 15);
    const int ac8_lo  = (lane >> 4);
    const int bg      = lane >> 3;
    const int brow_lo = wn * 64 + (bg >> 1) * 8 + (lane & 7);
    const int bc8_lo  = (bg & 1);

    uint32_t acc[4][8][2] = {};
    uint32_t af[4][4], bf[4][4];

    LOAD_CHUNK(0, 0);
    LOAD_CHUNK(1, 1);

    for (int c = 0; c < NCHUNK; c++) {
        const int stg = c & 1;
        CP_WAIT(1);
        __syncthreads();

        const uint32_t sA = sbase + (uint32_t)stg * STG_BYTES;
        const uint32_t sB = sA + STG_A_BYTES;

#pragma unroll
        for (int ks = 0; ks < 4; ks++) {
#pragma unroll
            for (int a = 0; a < 4; a++)
                ldm_x4(af[a], sA + swz128(arow_lo + a * 16, ks * 2 + ac8_lo));
#pragma unroll
            for (int b2 = 0; b2 < 4; b2++)
                ldm_x4(bf[b2], sB + swz128(brow_lo + b2 * 16, ks * 2 + bc8_lo));
#pragma unroll
            for (int a = 0; a < 4; a++)
#pragma unroll
                for (int b = 0; b < 8; b++)
                    mma16816h(acc[a][b], af[a], bf[b >> 1][(b & 1) * 2],
                                                bf[b >> 1][(b & 1) * 2 + 1]);
        }
        __syncthreads();   // all warps done reading stage before it is reloaded
        if (c + 2 < NCHUNK) LOAD_CHUNK(c + 2, stg);
    }

    // Epilogue: keys = qnorm[j] - 2*S; per-row top-2 over this warp's 64 cols.
    const int gid = lane >> 2, tig = lane & 3;
    const float INF = __int_as_float(0x7f800000);

    float qn[8][2];
#pragma unroll
    for (int b = 0; b < 8; b++) {
        int j = n0 + wn * 64 + b * 8 + tig * 2;
        qn[b][0] = g_qnorm[j];
        qn[b][1] = g_qnorm[j + 1];
    }

    float k1[8], k2[8]; int i1[8], i2[8];
#pragma unroll
    for (int s = 0; s < 8; s++) { k1[s] = k2[s] = INF; i1[s] = i2[s] = 0x7fffffff; }

#pragma unroll
    for (int a = 0; a < 4; a++)
#pragma unroll
        for (int b = 0; b < 8; b++) {
            int j = n0 + wn * 64 + b * 8 + tig * 2;
#pragma unroll
            for (int h = 0; h < 2; h++) {       // h=0: row gid, h=1: row gid+8
                int s = a * 2 + h;
                float2 v = __half22float2(*(const __half2*)&acc[a][b][h]);
#pragma unroll
                for (int e = 0; e < 2; e++) {
                    float key = fmaf(-2.f, e ? v.y : v.x, qn[b][e]);
                    int   jj  = j + e;
                    if (lex_less(key, jj, k1[s], i1[s])) {
                        k2[s] = k1[s]; i2[s] = i1[s]; k1[s] = key; i1[s] = jj;
                    } else if (lex_less(key, jj, k2[s], i2[s])) { k2[s] = key; i2[s] = jj; }
                }
            }
        }

#pragma unroll
    for (int off = 1; off <= 2; off <<= 1) {
#pragma unroll
        for (int s = 0; s < 8; s++) {
            float ok1 = __shfl_xor_sync(0xffffffffu, k1[s], off);
            int   oi1 = __shfl_xor_sync(0xffffffffu, i1[s], off);
            float ok2 = __shfl_xor_sync(0xffffffffu, k2[s], off);
            int   oi2 = __shfl_xor_sync(0xffffffffu, i2[s], off);
            merge2(k1[s], i1[s], k2[s], i2[s], ok1, oi1, ok2, oi2);
        }
    }

    if (tig == 0) {
        int ct = blockIdx.x * 4 + wn;
#pragma unroll
        for (int s = 0; s < 8; s++) {
            int row = m0 + wm * 64 + (s >> 1) * 16 + (s & 1) * 8 + gid;
            Top2 t; t.k1 = k1[s]; t.i1 = i1[s]; t.k2 = k2[s]; t.i2 = i2[s];
            g_partial[(size_t)row * PT + ct] = t;
        }
    }
}

// ---------------------------------------------------------------------------
// Kernel 3: 2 rows per 256-thread block (4 warps per row). Each warp loads
// 128 partials -> warp top-4; cross-warp merge in smem; the 4 warps rescore
// one candidate each (exact fp32); pick 2nd smallest; gather the queue row.
// (byte-identical to R12/R13)
// ---------------------------------------------------------------------------
__global__ void __launch_bounds__(256) reduce_rescore_kernel(const float* __restrict__ x,
                                                             const float* __restrict__ qp,
                                                             float* __restrict__ out) {
    const int tid  = threadIdx.x;
    const int wid  = tid >> 5;
    const int lane = tid & 31;
    const int rsel = wid >> 2;                 // 0/1: which of the 2 rows
    const int wr   = wid & 3;                  // warp-within-row 0..3
    const int row  = blockIdx.x * 2 + rsel;
    const float INF = __int_as_float(0x7f800000);

    __shared__ float s_k[2][4][4];
    __shared__ int   s_i[2][4][4];
    __shared__ float s_ek[2][4];
    __shared__ int   s_nn[2];

    float ks[4]; int is[4];
#pragma unroll
    for (int q = 0; q < 4; q++) { ks[q] = INF; is[q] = 0x7fffffff; }

    // each warp covers 128 consecutive partial slots
    const Top2* p = g_partial + (size_t)row * PT + wr * 128;
#pragma unroll
    for (int t = 0; t < 4; t++) {
        Top2 o = p[lane + t * 32];
        insert4(ks, is, o.k1, o.i1);
        insert4(ks, is, o.k2, o.i2);
    }
#pragma unroll
    for (int off = 16; off; off >>= 1) {
        float ok[4]; int oi[4];
#pragma unroll
        for (int q = 0; q < 4; q++) {
            ok[q] = __shfl_xor_sync(0xffffffffu, ks[q], off);
            oi[q] = __shfl_xor_sync(0xffffffffu, is[q], off);
        }
#pragma unroll
        for (int q = 0; q < 4; q++) insert4(ks, is, ok[q], oi[q]);
    }
    if (lane < 4) { s_k[rsel][wr][lane] = ks[lane]; s_i[rsel][wr][lane] = is[lane]; }
    __syncthreads();

    // every warp recomputes the row's global top-4 from the 16 smem entries
#pragma unroll
    for (int q = 0; q < 4; q++) { ks[q] = INF; is[q] = 0x7fffffff; }
#pragma unroll
    for (int w4 = 0; w4 < 4; w4++)
#pragma unroll
        for (int q = 0; q < 4; q++)
            insert4(ks, is, s_k[rsel][w4][q], s_i[rsel][w4][q]);

    // warp wr rescores candidate wr (exact fp32 dot over 512 dims)
    const int cand = is[wr];
    const float* xr = x + (size_t)row * DIM;
    const float* qr = queue_row(x, qp, cand);
    float s = 0.f;
#pragma unroll
    for (int kk = 0; kk < 4; kk++) {
        int k = (lane + 32 * kk) * 4;
        float4 a = *(const float4*)(xr + k);
        float4 b = *(const float4*)(qr + k);
        s += a.x * b.x + a.y * b.y + a.z * b.z + a.w * b.w;
    }
#pragma unroll
    for (int o = 16; o; o >>= 1) s += __shfl_xor_sync(0xffffffffu, s, o);
    if (lane == 0) s_ek[rsel][wr] = g_qnorm[cand] - 2.f * s;
    __syncthreads();

    // pick 2nd smallest (exact) among the 4 candidates; any one thread per row
    if (wr == 0 && lane == 0) {
        float ek[4];
#pragma unroll
        for (int q = 0; q < 4; q++) ek[q] = s_ek[rsel][q];
        int best = 0;
#pragma unroll
        for (int c = 1; c < 4; c++) if (lex_less(ek[c], is[c], ek[best], is[best])) best = c;
        int sec = (best == 0) ? 1 : 0;
#pragma unroll
        for (int c = 0; c < 4; c++)
            if (c != best && lex_less(ek[c], is[c], ek[sec], is[sec])) sec = c;
        s_nn[rsel] = is[sec];
    }
    __syncthreads();

    // gather: 128 threads per row copy 512 floats (1 float4 each)
    const int nn = s_nn[rsel];
    const int t128 = (wr << 5) | lane;          // 0..127 within the row group
    const float4* src = (const float4*)queue_row(x, qp, nn);
    float4*       dst = (float4*)(out + (size_t)row * DIM);
    dst[t128] = src[t128];
}

// ---------------------------------------------------------------------------
extern "C" void kernel_launch(void* const* d_in, const int* in_sizes, int n_in,
                              void* d_out, int out_size) {
    const float* x   = (const float*)d_in[0];   // (1024, 512)
    const float* qp  = (const float*)d_in[1];   // (32768, 512)
    float*       out = (float*)d_out;           // (1024, 512)

    cudaFuncSetAttribute(mma_top2_kernel,
                         cudaFuncAttributeMaxDynamicSharedMemorySize, SMEM_BYTES);

    prep_kernel<<<QSZ / 8, 256>>>(x, qp);

    dim3 grid(NTILES, MTILES);                  // (128, 8) = 1024 CTAs
    mma_top2_kernel<<<grid, 256, SMEM_BYTES>>>();

    reduce_rescore_kernel<<<BATCH / 2, 256>>>(x, qp, out);
}